// round 15
// baseline (speedup 1.0000x reference)
#include <cuda_runtime.h>
#include <cuda_fp16.h>
#include <cstdint>
#include <math.h>

// Shapes (fixed): B=2, L=2048, DM=1024, DI=2048, N=16, DC=4, DT=64
#define BB 2
#define LL 2048
#define DM 1024
#define DI 2048
#define NS 16
#define DC 4
#define DT 64
#define ROWS (BB*LL)          // 4096
#define XZW (2*DI)            // 4096
#define DBLW 128              // padded dbl row (dt 0..63 | B 64..79 | C 80..95 | pad)
#define CL 64                 // scan chunk length
#define NC (LL/CL)            // 32 chunks
#define CRS 8                 // conv rows per thread
#define PCTAS 296             // persistent CTAs (2 per SM x 148)

// ================= scratch (device globals) =================
__device__ __align__(256) __half g_xz[ROWS * XZW];                 // xi | z (fp16)
__device__ __align__(256) float g_dblp[4 * ROWS * DBLW];           // split-K partials
__device__ __align__(256) float g_dblr[ROWS * DBLW];               // reduced
__device__ __align__(256) __half g_delta[ROWS * DI];               // fp16 delta
__device__ __align__(256) float g_S[BB * NC * DI];                 // per-chunk sum(delta)
__device__ __align__(256) float g_hend[BB * NC * NS * DI];
__device__ __align__(256) float g_hstart[BB * NC * NS * DI];
// fp16 operands
__device__ __align__(256) __half g_xn[ROWS * DM];                  // LN out
__device__ __align__(256) __half g_y [ROWS * DI];                  // scan out
__device__ __align__(256) __half g_u [ROWS * DI];                  // conv+silu out
__device__ __align__(256) __half g_dt[ROWS * DT];                  // dt (single)
__device__ __align__(256) __half g_win [XZW * DM];                 // [4096,1024]
__device__ __align__(256) __half g_wout[DM * DI];                  // [1024,2048]
__device__ __align__(256) __half g_wx  [128 * DI];                 // [128,2048] padded
__device__ __align__(256) __half g_wdt [DI * DT];                  // [2048,64]

// ================= PTX helpers (baseline compute_103 ISA only) =================
__device__ __forceinline__ uint32_t smem_u32(const void* p) {
    uint32_t a;
    asm("{ .reg .u64 t; cvta.to.shared.u64 t, %1; cvt.u32.u64 %0, t; }" : "=r"(a) : "l"(p));
    return a;
}
__device__ __forceinline__ void cp_async16(uint32_t sa, const void* ga) {
    asm volatile("cp.async.cg.shared.global [%0], [%1], 16;" :: "r"(sa), "l"(ga));
}
__device__ __forceinline__ void cp_commit() {
    asm volatile("cp.async.commit_group;" ::: "memory");
}
__device__ __forceinline__ void cp_wait1() {
    asm volatile("cp.async.wait_group 1;" ::: "memory");
}
__device__ __forceinline__ void cp_wait0() {
    asm volatile("cp.async.wait_group 0;" ::: "memory");
}
__device__ __forceinline__ void ldsm4(uint32_t* r, uint32_t addr) {
    asm volatile("ldmatrix.sync.aligned.m8n8.x4.shared.b16 {%0,%1,%2,%3}, [%4];"
        : "=r"(r[0]), "=r"(r[1]), "=r"(r[2]), "=r"(r[3]) : "r"(addr));
}
__device__ __forceinline__ void mma_f16(float* d, const uint32_t* a, const uint32_t* b) {
    asm volatile("mma.sync.aligned.m16n8k16.row.col.f32.f16.f16.f32 "
        "{%0,%1,%2,%3}, {%4,%5,%6,%7}, {%8,%9}, {%0,%1,%2,%3};"
        : "+f"(d[0]), "+f"(d[1]), "+f"(d[2]), "+f"(d[3])
        : "r"(a[0]), "r"(a[1]), "r"(a[2]), "r"(a[3]), "r"(b[0]), "r"(b[1]));
}
// SW128 swizzled byte offset for (row, 16B-chunk c in 0..7) in a [rows x 128B] tile
__device__ __forceinline__ uint32_t sw128(int row, int c) {
    return (uint32_t)(row * 128 + ((c ^ (row & 7)) << 4));
}
__device__ __forceinline__ void unpack8(uint4 v, float* f) {
    __half2 h;
    h = *reinterpret_cast<__half2*>(&v.x); f[0] = __low2float(h); f[1] = __high2float(h);
    h = *reinterpret_cast<__half2*>(&v.y); f[2] = __low2float(h); f[3] = __high2float(h);
    h = *reinterpret_cast<__half2*>(&v.z); f[4] = __low2float(h); f[5] = __high2float(h);
    h = *reinterpret_cast<__half2*>(&v.w); f[6] = __low2float(h); f[7] = __high2float(h);
}

// ============ fused weight prep (4 transposes) + LayerNorm ============
__device__ __forceinline__ void trans_body(const float* __restrict__ W,
                                           __half* __restrict__ T,
                                           int K, int N, int bx, int by) {
    __shared__ float t[32][33];
    int tx = threadIdx.x & 31, ty = threadIdx.x >> 5;
    int n = bx * 32 + tx;
    int k0 = by * 32;
    #pragma unroll
    for (int i = 0; i < 4; i++) {
        int k = k0 + ty + i * 8;
        t[ty + i * 8][tx] = (n < N) ? W[(size_t)k * N + n] : 0.f;
    }
    __syncthreads();
    int kw = k0 + tx;
    #pragma unroll
    for (int i = 0; i < 4; i++) {
        int nn = bx * 32 + ty + i * 8;
        T[(size_t)nn * K + kw] = __float2half_rn(t[tx][ty + i * 8]);
    }
}

__device__ __forceinline__ void ln_body(const float* __restrict__ x,
                                        const float* __restrict__ gam,
                                        const float* __restrict__ bet,
                                        __half* __restrict__ xn, int row) {
    const float4* xr = reinterpret_cast<const float4*>(x + (size_t)row * DM);
    int t = threadIdx.x;
    float4 v = xr[t];
    float s  = v.x + v.y + v.z + v.w;
    float ss = v.x*v.x + v.y*v.y + v.z*v.z + v.w*v.w;
    #pragma unroll
    for (int o = 16; o > 0; o >>= 1) {
        s  += __shfl_xor_sync(0xffffffff, s,  o);
        ss += __shfl_xor_sync(0xffffffff, ss, o);
    }
    __shared__ float rs[8], rss[8];
    int wid = t >> 5, lid = t & 31;
    if (lid == 0) { rs[wid] = s; rss[wid] = ss; }
    __syncthreads();
    __shared__ float smu, srstd;
    if (t == 0) {
        float ts = 0.f, tss = 0.f;
        #pragma unroll
        for (int i = 0; i < 8; i++) { ts += rs[i]; tss += rss[i]; }
        float mu = ts / (float)DM;
        float var = tss / (float)DM - mu * mu;
        smu = mu; srstd = rsqrtf(var + 1e-5f);
    }
    __syncthreads();
    float mu = smu, rstd = srstd;
    const float4* g4 = reinterpret_cast<const float4*>(gam);
    const float4* b4 = reinterpret_cast<const float4*>(bet);
    float4 gg = g4[t], bb = b4[t];
    float o0 = (v.x - mu) * rstd * gg.x + bb.x;
    float o1 = (v.y - mu) * rstd * gg.y + bb.y;
    float o2 = (v.z - mu) * rstd * gg.z + bb.z;
    float o3 = (v.w - mu) * rstd * gg.w + bb.w;
    __half2* ph = reinterpret_cast<__half2*>(xn + (size_t)row * DM);
    ph[t*2]   = __halves2half2(__float2half_rn(o0), __float2half_rn(o1));
    ph[t*2+1] = __halves2half2(__float2half_rn(o2), __float2half_rn(o3));
}

__global__ void prep_kernel(const float* __restrict__ W_in,
                            const float* __restrict__ W_out,
                            const float* __restrict__ W_x,
                            const float* __restrict__ W_dt,
                            const float* __restrict__ x,
                            const float* __restrict__ ln_g,
                            const float* __restrict__ ln_b,
                            __half* __restrict__ win,
                            __half* __restrict__ wout,
                            __half* __restrict__ wx,
                            __half* __restrict__ wdt,
                            __half* __restrict__ xn) {
    int bid = blockIdx.x;
    if (bid < 4096) {
        trans_body(W_in, win, DM, XZW, bid & 127, bid >> 7);
    } else if (bid < 6144) {
        int b = bid - 4096;
        trans_body(W_out, wout, DI, DM, b & 31, b >> 5);
    } else if (bid < 6400) {
        int b = bid - 6144;
        trans_body(W_x, wx, DI, 96, b & 3, b >> 2);
    } else if (bid < 6528) {
        int b = bid - 6400;
        trans_body(W_dt, wdt, DT, DI, b & 63, b >> 6);
    } else {
        ln_body(x, ln_g, ln_b, xn, bid - 6528);
    }
}

// ========== unified fp16 GEMM, BK=64, persistent tile loop ==========
// Tiles are 128x128, linear index tile = ty*ntx + tx; CTAs stride by gridDim.x.
// EPI 0: fp16 out. 1: fp32 out += E[off]. 2: softplus(v+E[col]) -> fp16. 3: fp32.
#define STG1 32768
#define SMEM1 (3 * STG1)
template<int EPI>
__global__ void __launch_bounds__(256, 2) gemmk(
    const __half* __restrict__ A, const __half* __restrict__ B,
    const float* __restrict__ E, void* __restrict__ Cv,
    int lda, int ldc, int nkt, size_t zstride, int ntx, int ntiles) {
    extern __shared__ __align__(128) char sm[];
    const int tid = threadIdx.x, lane = tid & 31, wid = tid >> 5;
    const int wm = (wid >> 2) * 64, wn = (wid & 3) * 32;
    const int kt0 = blockIdx.z * nkt;
    const size_t coff = (size_t)blockIdx.z * zstride;
    const uint32_t sb = smem_u32(sm);
    const int lrow = lane & 15, lk = lane >> 4;

    for (int tile = blockIdx.x; tile < ntiles; tile += gridDim.x) {
        const int m0 = (tile / ntx) * 128, n0 = (tile % ntx) * 128;

        float d[4][4][4];
        #pragma unroll
        for (int a = 0; a < 4; a++)
            #pragma unroll
            for (int b = 0; b < 4; b++)
                #pragma unroll
                for (int c = 0; c < 4; c++) d[a][b][c] = 0.f;

        auto load_tile = [&](int kt, int stage) {
            uint32_t dst = sb + stage * STG1;
            #pragma unroll
            for (int j = 0; j < 8; j++) {
                int chunk = tid + j * 256;        // 0..2047
                int t = chunk >> 10;              // 0:A 1:B (uniform per j)
                int w = chunk & 1023;
                int row = w >> 3, c = w & 7;
                const __half* src = (t == 0) ? A : B;
                int g0 = (t == 0 ? m0 : n0) + row;
                const void* gp = (const char*)(src + (size_t)g0 * lda + (kt0 + kt) * 64) + c * 16;
                cp_async16(dst + t * 16384 + sw128(row, c), gp);
            }
            cp_commit();
        };

        load_tile(0, 0);
        if (nkt > 1) load_tile(1, 1);

        for (int i = 0; i < nkt; i++) {
            if (i + 1 < nkt) cp_wait1(); else cp_wait0();
            __syncthreads();
            if (i + 2 < nkt) load_tile(i + 2, (i + 2) % 3);

            uint32_t base = sb + (i % 3) * STG1;
            #pragma unroll
            for (int ks = 0; ks < 4; ks++) {
                uint32_t a[4][4], bf[4][2];
                #pragma unroll
                for (int mi = 0; mi < 4; mi++)
                    ldsm4(a[mi], base + sw128(wm + mi * 16 + lrow, ks * 2 + lk));
                #pragma unroll
                for (int nj = 0; nj < 2; nj++) {
                    uint32_t t4[4];
                    ldsm4(t4, base + 16384 + sw128(wn + nj * 16 + lrow, ks * 2 + lk));
                    bf[nj*2][0] = t4[0]; bf[nj*2][1] = t4[2];
                    bf[nj*2+1][0] = t4[1]; bf[nj*2+1][1] = t4[3];
                }
                #pragma unroll
                for (int mi = 0; mi < 4; mi++)
                    #pragma unroll
                    for (int ni = 0; ni < 4; ni++)
                        mma_f16(d[mi][ni], a[mi], bf[ni]);
            }
        }

        #pragma unroll
        for (int mi = 0; mi < 4; mi++) {
            #pragma unroll
            for (int ni = 0; ni < 4; ni++) {
                int r = m0 + wm + mi * 16 + (lane >> 2);
                int col = n0 + wn + ni * 8 + (lane & 3) * 2;
                #pragma unroll
                for (int h = 0; h < 2; h++) {
                    int rr = r + h * 8;
                    float v0 = d[mi][ni][h*2], v1 = d[mi][ni][h*2+1];
                    size_t off = coff + (size_t)rr * ldc + col;
                    if (EPI == 0) {
                        __half* C = (__half*)Cv;
                        *reinterpret_cast<__half2*>(C + off) =
                            __halves2half2(__float2half_rn(v0), __float2half_rn(v1));
                    } else if (EPI == 1) {
                        float* C = (float*)Cv;
                        v0 += E[off]; v1 += E[off + 1];
                        *reinterpret_cast<float2*>(C + off) = make_float2(v0, v1);
                    } else if (EPI == 2) {
                        float a0 = v0 + E[col], a1 = v1 + E[col + 1];
                        v0 = (a0 > 20.f) ? a0 : __logf(1.f + __expf(a0));
                        v1 = (a1 > 20.f) ? a1 : __logf(1.f + __expf(a1));
                        __half* C = (__half*)Cv;
                        *reinterpret_cast<__half2*>(C + off) =
                            __halves2half2(__float2half_rn(v0), __float2half_rn(v1));
                    } else {
                        float* C = (float*)Cv;
                        *reinterpret_cast<float2*>(C + off) = make_float2(v0, v1);
                    }
                }
            }
        }
        __syncthreads();
    }
}

// ============ reduce split-K partials -> dblr; dt -> fp16 ============
__global__ void reduce_dbl_kernel(const float* __restrict__ dblp,
                                  float* __restrict__ dblr,
                                  __half* __restrict__ dt) {
    int i = blockIdx.x * 256 + threadIdx.x;
    if (i >= ROWS * DBLW) return;
    float s = dblp[i] + dblp[i + ROWS*DBLW] + dblp[i + 2*ROWS*DBLW] + dblp[i + 3*ROWS*DBLW];
    dblr[i] = s;
    int col = i & (DBLW - 1);
    if (col < DT) {
        int row = i >> 7;
        dt[row * DT + col] = __float2half_rn(s);
    }
}

// ======== vectorized depthwise conv + SiLU -> u (8 ch x 8 rows / thread) ========
__global__ void conv_silu_kernel(const __half* __restrict__ xz,
                                 const float* __restrict__ cw,
                                 const float* __restrict__ cb,
                                 __half* __restrict__ u) {
    int idx = blockIdx.x * 256 + threadIdx.x;
    int ncg = DI / 8;                  // 256 channel groups
    int cg = idx & (ncg - 1);
    int strip = idx >> 8;              // 0 .. ROWS/CRS-1
    int d0 = cg * 8;
    int row0 = strip * CRS;
    int b = row0 >> 11;
    int l0 = row0 & (LL - 1);

    float w[8][4], bias[8];
    #pragma unroll
    for (int c = 0; c < 8; c++) {
        float4 wv = reinterpret_cast<const float4*>(cw)[d0 + c];
        w[c][0] = wv.x; w[c][1] = wv.y; w[c][2] = wv.z; w[c][3] = wv.w;
        bias[c] = cb[d0 + c];
    }

    size_t xbase = ((size_t)b * LL + l0) * XZW + d0;
    size_t ubase = ((size_t)b * LL + l0) * DI + d0;

    float xw[3][8];
    #pragma unroll
    for (int k = 0; k < 3; k++) {
        int lk = l0 - 3 + k;
        if (lk >= 0) {
            uint4 v = *reinterpret_cast<const uint4*>(xz + xbase + (size_t)(k - 3) * XZW);
            unpack8(v, xw[k]);
        } else {
            #pragma unroll
            for (int c = 0; c < 8; c++) xw[k][c] = 0.f;
        }
    }

    #pragma unroll
    for (int j = 0; j < CRS; j++) {
        uint4 v = *reinterpret_cast<const uint4*>(xz + xbase + (size_t)j * XZW);
        float cur[8];
        unpack8(v, cur);
        uint4 ov;
        __half2* oh = reinterpret_cast<__half2*>(&ov);
        #pragma unroll
        for (int c = 0; c < 8; c += 2) {
            float a0 = bias[c]   + xw[0][c]  *w[c][0]   + xw[1][c]  *w[c][1]   + xw[2][c]  *w[c][2]   + cur[c]  *w[c][3];
            float a1 = bias[c+1] + xw[0][c+1]*w[c+1][0] + xw[1][c+1]*w[c+1][1] + xw[2][c+1]*w[c+1][2] + cur[c+1]*w[c+1][3];
            float r0 = a0 / (1.f + __expf(-a0));
            float r1 = a1 / (1.f + __expf(-a1));
            oh[c >> 1] = __halves2half2(__float2half_rn(r0), __float2half_rn(r1));
        }
        *reinterpret_cast<uint4*>(u + ubase + (size_t)j * DI) = ov;
        #pragma unroll
        for (int c = 0; c < 8; c++) { xw[0][c] = xw[1][c]; xw[1][c] = xw[2][c]; xw[2][c] = cur[c]; }
    }
}

// ================= chunked parallel scan =================
__device__ __forceinline__ bool load_A(const float* __restrict__ A_log, int d, float* A) {
    bool fast = true;
    #pragma unroll
    for (int n = 0; n < NS; n++) {
        A[n] = -__expf(A_log[d * NS + n]);
        fast = fast && (fabsf(A[n] + (float)(n + 1)) < 1e-5f * (float)(n + 1));
    }
    return fast;
}
__device__ __forceinline__ void pow_tree(float p, float* pw) {
    pw[0] = p;
    #pragma unroll
    for (int k = 1; k < NS; k++) pw[k] = pw[(k - 1) >> 1] * pw[k >> 1];
}

__global__ void scan_pass1(const float* __restrict__ dblr,
                           const __half* __restrict__ delta,
                           const __half* __restrict__ u,
                           const float* __restrict__ A_log,
                           float* __restrict__ S_out,
                           float* __restrict__ hend) {
    int d = blockIdx.x * 256 + threadIdx.x;
    int c = blockIdx.y, b = blockIdx.z;
    float A[NS];
    bool fast = load_A(A_log, d, A);
    float h[NS];
    #pragma unroll
    for (int n = 0; n < NS; n++) h[n] = 0.f;
    float S = 0.f;
    size_t rbase = (size_t)b * LL + (size_t)c * CL;
    for (int j = 0; j < CL; j++) {
        size_t row = rbase + j;
        float dl = __half2float(delta[row * DI + d]);
        float ul = __half2float(u[row * DI + d]);
        const float4* Bp = reinterpret_cast<const float4*>(dblr + row * DBLW + DT);
        float4 B0 = Bp[0], B1 = Bp[1], B2 = Bp[2], B3 = Bp[3];
        float Bv[NS] = {B0.x,B0.y,B0.z,B0.w, B1.x,B1.y,B1.z,B1.w,
                        B2.x,B2.y,B2.z,B2.w, B3.x,B3.y,B3.z,B3.w};
        S += dl;
        float su = dl * ul;
        if (fast) {
            float pw[NS];
            pow_tree(__expf(-dl), pw);
            #pragma unroll
            for (int n = 0; n < NS; n++) h[n] = fmaf(pw[n], h[n], su * Bv[n]);
        } else {
            #pragma unroll
            for (int n = 0; n < NS; n++) h[n] = fmaf(__expf(dl * A[n]), h[n], su * Bv[n]);
        }
    }
    size_t cb = (size_t)b * NC + c;
    S_out[cb * DI + d] = S;
    #pragma unroll
    for (int n = 0; n < NS; n++) hend[(cb * NS + n) * DI + d] = h[n];
}

__global__ void scan_pass2(const float* __restrict__ S_in,
                           const float* __restrict__ hend,
                           const float* __restrict__ A_log,
                           float* __restrict__ hstart) {
    int d = blockIdx.x * 256 + threadIdx.x;
    int b = blockIdx.y;
    float A[NS];
    bool fast = load_A(A_log, d, A);
    float h[NS];
    #pragma unroll
    for (int n = 0; n < NS; n++) h[n] = 0.f;
    for (int c = 0; c < NC; c++) {
        size_t cb = (size_t)b * NC + c;
        #pragma unroll
        for (int n = 0; n < NS; n++) hstart[(cb * NS + n) * DI + d] = h[n];
        float S = S_in[cb * DI + d];
        if (fast) {
            float pw[NS];
            pow_tree(__expf(-S), pw);
            #pragma unroll
            for (int n = 0; n < NS; n++)
                h[n] = fmaf(pw[n], h[n], hend[(cb * NS + n) * DI + d]);
        } else {
            #pragma unroll
            for (int n = 0; n < NS; n++)
                h[n] = fmaf(__expf(S * A[n]), h[n], hend[(cb * NS + n) * DI + d]);
        }
    }
}

__global__ void scan_pass3(const float* __restrict__ dblr,
                           const __half* __restrict__ delta,
                           const __half* __restrict__ u,
                           const __half* __restrict__ xz,
                           const float* __restrict__ A_log,
                           const float* __restrict__ Dskip,
                           const float* __restrict__ hstart,
                           __half* __restrict__ y) {
    int d = blockIdx.x * 256 + threadIdx.x;
    int c = blockIdx.y, b = blockIdx.z;
    float A[NS];
    bool fast = load_A(A_log, d, A);
    float Dd = Dskip[d];
    size_t cb = (size_t)b * NC + c;
    float h[NS];
    #pragma unroll
    for (int n = 0; n < NS; n++) h[n] = hstart[(cb * NS + n) * DI + d];
    size_t rbase = (size_t)b * LL + (size_t)c * CL;
    for (int j = 0; j < CL; j++) {
        size_t row = rbase + j;
        float dl = __half2float(delta[row * DI + d]);
        float ul = __half2float(u[row * DI + d]);
        float zl = __half2float(xz[row * XZW + DI + d]);
        const float4* Bp = reinterpret_cast<const float4*>(dblr + row * DBLW + DT);
        float4 B0 = Bp[0], B1 = Bp[1], B2 = Bp[2], B3 = Bp[3];
        float4 C0 = Bp[4], C1 = Bp[5], C2 = Bp[6], C3 = Bp[7];
        float Bv[NS] = {B0.x,B0.y,B0.z,B0.w, B1.x,B1.y,B1.z,B1.w,
                        B2.x,B2.y,B2.z,B2.w, B3.x,B3.y,B3.z,B3.w};
        float Cv[NS] = {C0.x,C0.y,C0.z,C0.w, C1.x,C1.y,C1.z,C1.w,
                        C2.x,C2.y,C2.z,C2.w, C3.x,C3.y,C3.z,C3.w};
        float su = dl * ul;
        float a0 = 0.f, a1 = 0.f, a2 = 0.f, a3 = 0.f;
        if (fast) {
            float pw[NS];
            pow_tree(__expf(-dl), pw);
            #pragma unroll
            for (int n = 0; n < NS; n++) {
                h[n] = fmaf(pw[n], h[n], su * Bv[n]);
                float* ap = (n & 2) ? ((n & 1) ? &a3 : &a2) : ((n & 1) ? &a1 : &a0);
                *ap = fmaf(h[n], Cv[n], *ap);
            }
        } else {
            #pragma unroll
            for (int n = 0; n < NS; n++) {
                h[n] = fmaf(__expf(dl * A[n]), h[n], su * Bv[n]);
                float* ap = (n & 2) ? ((n & 1) ? &a3 : &a2) : ((n & 1) ? &a1 : &a0);
                *ap = fmaf(h[n], Cv[n], *ap);
            }
        }
        float acc = (a0 + a1) + (a2 + a3);
        float sz = zl / (1.f + __expf(-zl));
        y[row * DI + d] = __float2half_rn(fmaf(ul, Dd, acc) * sz);
    }
}

// ================= launch =================
extern "C" void kernel_launch(void* const* d_in, const int* in_sizes, int n_in,
                              void* d_out, int out_size) {
    const float* x      = (const float*)d_in[0];
    const float* ln_g   = (const float*)d_in[1];
    const float* ln_b   = (const float*)d_in[2];
    const float* W_in   = (const float*)d_in[3];
    const float* conv_w = (const float*)d_in[4];
    const float* conv_b = (const float*)d_in[5];
    const float* W_x    = (const float*)d_in[6];
    const float* W_dt   = (const float*)d_in[7];
    const float* b_dt   = (const float*)d_in[8];
    const float* A_log  = (const float*)d_in[9];
    const float* Dskip  = (const float*)d_in[10];
    const float* W_out  = (const float*)d_in[11];
    float* out = (float*)d_out;

    float *dblp, *dblr, *Ssum, *hend, *hstart;
    __half *xz, *xn, *y, *u, *dt, *delta;
    __half *win, *wout, *wx, *wdt;
    cudaGetSymbolAddress((void**)&xz, g_xz);
    cudaGetSymbolAddress((void**)&dblp, g_dblp);
    cudaGetSymbolAddress((void**)&dblr, g_dblr);
    cudaGetSymbolAddress((void**)&delta, g_delta);
    cudaGetSymbolAddress((void**)&Ssum, g_S);
    cudaGetSymbolAddress((void**)&hend, g_hend);
    cudaGetSymbolAddress((void**)&hstart, g_hstart);
    cudaGetSymbolAddress((void**)&xn, g_xn);
    cudaGetSymbolAddress((void**)&y, g_y);
    cudaGetSymbolAddress((void**)&u, g_u);
    cudaGetSymbolAddress((void**)&dt, g_dt);
    cudaGetSymbolAddress((void**)&win, g_win);
    cudaGetSymbolAddress((void**)&wout, g_wout);
    cudaGetSymbolAddress((void**)&wx, g_wx);
    cudaGetSymbolAddress((void**)&wdt, g_wdt);

    cudaFuncSetAttribute(gemmk<0>, cudaFuncAttributeMaxDynamicSharedMemorySize, SMEM1);
    cudaFuncSetAttribute(gemmk<1>, cudaFuncAttributeMaxDynamicSharedMemorySize, SMEM1);
    cudaFuncSetAttribute(gemmk<2>, cudaFuncAttributeMaxDynamicSharedMemorySize, SMEM1);
    cudaFuncSetAttribute(gemmk<3>, cudaFuncAttributeMaxDynamicSharedMemorySize, SMEM1);

    // 0. fused weight prep (4 transposes) + LayerNorm, one launch
    prep_kernel<<<6528 + ROWS, 256>>>(W_in, W_out, W_x, W_dt, x, ln_g, ln_b,
                                      win, wout, wx, wdt, xn);

    // 1. xz = xn @ W_in  [4096,1024]x[1024,4096] -> fp16 (persistent, 1024 tiles)
    gemmk<0><<<dim3(PCTAS, 1, 1), 256, SMEM1>>>(xn, win,
        nullptr, xz, DM, XZW, DM/64, 0, XZW/128, (ROWS/128)*(XZW/128));

    // 2. conv + silu -> u fp16 (vectorized, sliding window)
    conv_silu_kernel<<<(ROWS/CRS) * (DI/8) / 256, 256>>>(xz, conv_w, conv_b, u);

    // 3. dbl = u @ W_x   (split-K x4 -> fp32 partials; 32 tiles)
    gemmk<3><<<dim3(32, 1, 4), 256, SMEM1>>>(u, wx,
        nullptr, dblp, DI, DBLW, (DI/64)/4, (size_t)ROWS * DBLW, 1, ROWS/128);

    // 4. reduce + dt fp16
    reduce_dbl_kernel<<<(ROWS*DBLW)/256, 256>>>(dblp, dblr, dt);

    // 5. delta = softplus(dt @ W_dt + b_dt) -> fp16  (persistent, 512 tiles)
    gemmk<2><<<dim3(PCTAS, 1, 1), 256, SMEM1>>>(dt, wdt,
        b_dt, delta, DT, DI, DT/64, 0, DI/128, (ROWS/128)*(DI/128));

    // 6. chunked scan -> y fp16
    scan_pass1<<<dim3(DI/256, NC, BB), 256>>>(dblr, delta, u, A_log, Ssum, hend);
    scan_pass2<<<dim3(DI/256, BB), 256>>>(Ssum, hend, A_log, hstart);
    scan_pass3<<<dim3(DI/256, NC, BB), 256>>>(dblr, delta, u, xz, A_log, Dskip,
                                              hstart, y);

    // 7. out = x + y @ W_out   (256 tiles, single wave)
    gemmk<1><<<dim3(256, 1, 1), 256, SMEM1>>>(y, wout,
        x, out, DI, DM, DI/64, 0, DM/128, (ROWS/128)*(DM/128));
}

// round 16
// speedup vs baseline: 1.0370x; 1.0370x over previous
#include <cuda_runtime.h>
#include <cuda_fp16.h>
#include <cstdint>
#include <math.h>

// Shapes (fixed): B=2, L=2048, DM=1024, DI=2048, N=16, DC=4, DT=64
#define BB 2
#define LL 2048
#define DM 1024
#define DI 2048
#define NS 16
#define DC 4
#define DT 64
#define ROWS (BB*LL)          // 4096
#define XZW (2*DI)            // 4096
#define DBLW 128              // padded dbl row (dt 0..63 | B 64..79 | C 80..95 | pad)
#define CL 64                 // scan chunk length
#define NC (LL/CL)            // 32 chunks
#define CRS 8                 // conv rows per thread

// ================= scratch (device globals) =================
__device__ __align__(256) __half g_xz[ROWS * XZW];                 // xi | z (fp16)
__device__ __align__(256) float g_dblp[4 * ROWS * DBLW];           // split-K partials
__device__ __align__(256) float g_dblr[ROWS * DBLW];               // reduced
__device__ __align__(256) __half g_delta[ROWS * DI];               // fp16 delta
__device__ __align__(256) float g_S[BB * NC * DI];                 // per-chunk sum(delta)
__device__ __align__(256) float g_hend[BB * NC * NS * DI];
__device__ __align__(256) float g_hstart[BB * NC * NS * DI];
// fp16 operands
__device__ __align__(256) __half g_xn[ROWS * DM];                  // LN out
__device__ __align__(256) __half g_y [ROWS * DI];                  // scan out
__device__ __align__(256) __half g_u [ROWS * DI];                  // conv+silu out
__device__ __align__(256) __half g_dt[ROWS * DT];                  // dt (single)
__device__ __align__(256) __half g_win [XZW * DM];                 // [4096,1024]
__device__ __align__(256) __half g_wout[DM * DI];                  // [1024,2048]
__device__ __align__(256) __half g_wx  [128 * DI];                 // [128,2048] padded
__device__ __align__(256) __half g_wdt [DI * DT];                  // [2048,64]

// ================= PTX helpers (baseline compute_103 ISA only) =================
__device__ __forceinline__ uint32_t smem_u32(const void* p) {
    uint32_t a;
    asm("{ .reg .u64 t; cvta.to.shared.u64 t, %1; cvt.u32.u64 %0, t; }" : "=r"(a) : "l"(p));
    return a;
}
__device__ __forceinline__ void cp_async16(uint32_t sa, const void* ga) {
    asm volatile("cp.async.cg.shared.global [%0], [%1], 16;" :: "r"(sa), "l"(ga));
}
__device__ __forceinline__ void cp_commit() {
    asm volatile("cp.async.commit_group;" ::: "memory");
}
__device__ __forceinline__ void cp_wait1() {
    asm volatile("cp.async.wait_group 1;" ::: "memory");
}
__device__ __forceinline__ void cp_wait0() {
    asm volatile("cp.async.wait_group 0;" ::: "memory");
}
__device__ __forceinline__ void ldsm4(uint32_t* r, uint32_t addr) {
    asm volatile("ldmatrix.sync.aligned.m8n8.x4.shared.b16 {%0,%1,%2,%3}, [%4];"
        : "=r"(r[0]), "=r"(r[1]), "=r"(r[2]), "=r"(r[3]) : "r"(addr));
}
__device__ __forceinline__ void mma_f16(float* d, const uint32_t* a, const uint32_t* b) {
    asm volatile("mma.sync.aligned.m16n8k16.row.col.f32.f16.f16.f32 "
        "{%0,%1,%2,%3}, {%4,%5,%6,%7}, {%8,%9}, {%0,%1,%2,%3};"
        : "+f"(d[0]), "+f"(d[1]), "+f"(d[2]), "+f"(d[3])
        : "r"(a[0]), "r"(a[1]), "r"(a[2]), "r"(a[3]), "r"(b[0]), "r"(b[1]));
}
// SW128 swizzled byte offset for (row, 16B-chunk c in 0..7) in a [rows x 128B] tile
__device__ __forceinline__ uint32_t sw128(int row, int c) {
    return (uint32_t)(row * 128 + ((c ^ (row & 7)) << 4));
}
__device__ __forceinline__ void unpack8(uint4 v, float* f) {
    __half2 h;
    h = *reinterpret_cast<__half2*>(&v.x); f[0] = __low2float(h); f[1] = __high2float(h);
    h = *reinterpret_cast<__half2*>(&v.y); f[2] = __low2float(h); f[3] = __high2float(h);
    h = *reinterpret_cast<__half2*>(&v.z); f[4] = __low2float(h); f[5] = __high2float(h);
    h = *reinterpret_cast<__half2*>(&v.w); f[6] = __low2float(h); f[7] = __high2float(h);
}

// ============ fused weight prep (4 transposes) + LayerNorm ============
__device__ __forceinline__ void trans_body(const float* __restrict__ W,
                                           __half* __restrict__ T,
                                           int K, int N, int bx, int by) {
    __shared__ float t[32][33];
    int tx = threadIdx.x & 31, ty = threadIdx.x >> 5;
    int n = bx * 32 + tx;
    int k0 = by * 32;
    #pragma unroll
    for (int i = 0; i < 4; i++) {
        int k = k0 + ty + i * 8;
        t[ty + i * 8][tx] = (n < N) ? W[(size_t)k * N + n] : 0.f;
    }
    __syncthreads();
    int kw = k0 + tx;
    #pragma unroll
    for (int i = 0; i < 4; i++) {
        int nn = bx * 32 + ty + i * 8;
        T[(size_t)nn * K + kw] = __float2half_rn(t[tx][ty + i * 8]);
    }
}

__device__ __forceinline__ void ln_body(const float* __restrict__ x,
                                        const float* __restrict__ gam,
                                        const float* __restrict__ bet,
                                        __half* __restrict__ xn, int row) {
    const float4* xr = reinterpret_cast<const float4*>(x + (size_t)row * DM);
    int t = threadIdx.x;
    float4 v = xr[t];
    float s  = v.x + v.y + v.z + v.w;
    float ss = v.x*v.x + v.y*v.y + v.z*v.z + v.w*v.w;
    #pragma unroll
    for (int o = 16; o > 0; o >>= 1) {
        s  += __shfl_xor_sync(0xffffffff, s,  o);
        ss += __shfl_xor_sync(0xffffffff, ss, o);
    }
    __shared__ float rs[8], rss[8];
    int wid = t >> 5, lid = t & 31;
    if (lid == 0) { rs[wid] = s; rss[wid] = ss; }
    __syncthreads();
    __shared__ float smu, srstd;
    if (t == 0) {
        float ts = 0.f, tss = 0.f;
        #pragma unroll
        for (int i = 0; i < 8; i++) { ts += rs[i]; tss += rss[i]; }
        float mu = ts / (float)DM;
        float var = tss / (float)DM - mu * mu;
        smu = mu; srstd = rsqrtf(var + 1e-5f);
    }
    __syncthreads();
    float mu = smu, rstd = srstd;
    const float4* g4 = reinterpret_cast<const float4*>(gam);
    const float4* b4 = reinterpret_cast<const float4*>(bet);
    float4 gg = g4[t], bb = b4[t];
    float o0 = (v.x - mu) * rstd * gg.x + bb.x;
    float o1 = (v.y - mu) * rstd * gg.y + bb.y;
    float o2 = (v.z - mu) * rstd * gg.z + bb.z;
    float o3 = (v.w - mu) * rstd * gg.w + bb.w;
    __half2* ph = reinterpret_cast<__half2*>(xn + (size_t)row * DM);
    ph[t*2]   = __halves2half2(__float2half_rn(o0), __float2half_rn(o1));
    ph[t*2+1] = __halves2half2(__float2half_rn(o2), __float2half_rn(o3));
}

__global__ void prep_kernel(const float* __restrict__ W_in,
                            const float* __restrict__ W_out,
                            const float* __restrict__ W_x,
                            const float* __restrict__ W_dt,
                            const float* __restrict__ x,
                            const float* __restrict__ ln_g,
                            const float* __restrict__ ln_b,
                            __half* __restrict__ win,
                            __half* __restrict__ wout,
                            __half* __restrict__ wx,
                            __half* __restrict__ wdt,
                            __half* __restrict__ xn) {
    int bid = blockIdx.x;
    if (bid < 4096) {
        trans_body(W_in, win, DM, XZW, bid & 127, bid >> 7);
    } else if (bid < 6144) {
        int b = bid - 4096;
        trans_body(W_out, wout, DI, DM, b & 31, b >> 5);
    } else if (bid < 6400) {
        int b = bid - 6144;
        trans_body(W_x, wx, DI, 96, b & 3, b >> 2);
    } else if (bid < 6528) {
        int b = bid - 6400;
        trans_body(W_dt, wdt, DT, DI, b & 63, b >> 6);
    } else {
        ln_body(x, ln_g, ln_b, xn, bid - 6528);
    }
}

// ================= unified fp16 GEMM, BK=64, 1 mma pass =================
// EPI 0: fp16 out. 1: fp32 out += E[off]. 2: softplus(v+E[col]) -> fp16. 3: fp32.
#define STG1 32768
#define SMEM1 (3 * STG1)
template<int EPI>
__global__ void __launch_bounds__(256, 2) gemmk(
    const __half* __restrict__ A, const __half* __restrict__ B,
    const float* __restrict__ E, void* __restrict__ Cv,
    int lda, int ldc, int nkt, size_t zstride) {
    extern __shared__ __align__(128) char sm[];
    const int tid = threadIdx.x, lane = tid & 31, wid = tid >> 5;
    const int m0 = blockIdx.y * 128, n0 = blockIdx.x * 128;
    const int wm = (wid >> 2) * 64, wn = (wid & 3) * 32;
    const int kt0 = blockIdx.z * nkt;
    const size_t coff = (size_t)blockIdx.z * zstride;
    const uint32_t sb = smem_u32(sm);

    float d[4][4][4];
    #pragma unroll
    for (int a = 0; a < 4; a++)
        #pragma unroll
        for (int b = 0; b < 4; b++)
            #pragma unroll
            for (int c = 0; c < 4; c++) d[a][b][c] = 0.f;

    // stage: A [128 x 64 half] 16KB, B [128 x 64 half] 16KB; 128B rows SW128.
    auto load_tile = [&](int kt, int stage) {
        uint32_t dst = sb + stage * STG1;
        #pragma unroll
        for (int j = 0; j < 8; j++) {
            int chunk = tid + j * 256;        // 0..2047
            int t = chunk >> 10;              // 0:A 1:B (uniform per j)
            int w = chunk & 1023;
            int row = w >> 3, c = w & 7;
            const __half* src = (t == 0) ? A : B;
            int g0 = (t == 0 ? m0 : n0) + row;
            const void* gp = (const char*)(src + (size_t)g0 * lda + (kt0 + kt) * 64) + c * 16;
            cp_async16(dst + t * 16384 + sw128(row, c), gp);
        }
        cp_commit();
    };

    load_tile(0, 0);
    if (nkt > 1) load_tile(1, 1);

    const int lrow = lane & 15, lk = lane >> 4;
    for (int i = 0; i < nkt; i++) {
        if (i + 1 < nkt) cp_wait1(); else cp_wait0();
        __syncthreads();
        if (i + 2 < nkt) load_tile(i + 2, (i + 2) % 3);

        uint32_t base = sb + (i % 3) * STG1;
        #pragma unroll
        for (int ks = 0; ks < 4; ks++) {
            uint32_t a[4][4], bf[4][2];
            #pragma unroll
            for (int mi = 0; mi < 4; mi++)
                ldsm4(a[mi], base + sw128(wm + mi * 16 + lrow, ks * 2 + lk));
            #pragma unroll
            for (int nj = 0; nj < 2; nj++) {
                uint32_t t4[4];
                ldsm4(t4, base + 16384 + sw128(wn + nj * 16 + lrow, ks * 2 + lk));
                bf[nj*2][0] = t4[0]; bf[nj*2][1] = t4[2];
                bf[nj*2+1][0] = t4[1]; bf[nj*2+1][1] = t4[3];
            }
            #pragma unroll
            for (int mi = 0; mi < 4; mi++)
                #pragma unroll
                for (int ni = 0; ni < 4; ni++)
                    mma_f16(d[mi][ni], a[mi], bf[ni]);
        }
    }

    #pragma unroll
    for (int mi = 0; mi < 4; mi++) {
        #pragma unroll
        for (int ni = 0; ni < 4; ni++) {
            int r = m0 + wm + mi * 16 + (lane >> 2);
            int col = n0 + wn + ni * 8 + (lane & 3) * 2;
            #pragma unroll
            for (int h = 0; h < 2; h++) {
                int rr = r + h * 8;
                float v0 = d[mi][ni][h*2], v1 = d[mi][ni][h*2+1];
                size_t off = coff + (size_t)rr * ldc + col;
                if (EPI == 0) {
                    __half* C = (__half*)Cv;
                    *reinterpret_cast<__half2*>(C + off) =
                        __halves2half2(__float2half_rn(v0), __float2half_rn(v1));
                } else if (EPI == 1) {
                    float* C = (float*)Cv;
                    v0 += E[off]; v1 += E[off + 1];
                    *reinterpret_cast<float2*>(C + off) = make_float2(v0, v1);
                } else if (EPI == 2) {
                    float a0 = v0 + E[col], a1 = v1 + E[col + 1];
                    v0 = (a0 > 20.f) ? a0 : __logf(1.f + __expf(a0));
                    v1 = (a1 > 20.f) ? a1 : __logf(1.f + __expf(a1));
                    __half* C = (__half*)Cv;
                    *reinterpret_cast<__half2*>(C + off) =
                        __halves2half2(__float2half_rn(v0), __float2half_rn(v1));
                } else {
                    float* C = (float*)Cv;
                    *reinterpret_cast<float2*>(C + off) = make_float2(v0, v1);
                }
            }
        }
    }
}

// ============ reduce split-K partials -> dblr; dt -> fp16 ============
__global__ void reduce_dbl_kernel(const float* __restrict__ dblp,
                                  float* __restrict__ dblr,
                                  __half* __restrict__ dt) {
    int i = blockIdx.x * 256 + threadIdx.x;
    if (i >= ROWS * DBLW) return;
    float s = dblp[i] + dblp[i + ROWS*DBLW] + dblp[i + 2*ROWS*DBLW] + dblp[i + 3*ROWS*DBLW];
    dblr[i] = s;
    int col = i & (DBLW - 1);
    if (col < DT) {
        int row = i >> 7;
        dt[row * DT + col] = __float2half_rn(s);
    }
}

// ======== vectorized depthwise conv + SiLU -> u (8 ch x 8 rows / thread) ========
__global__ void conv_silu_kernel(const __half* __restrict__ xz,
                                 const float* __restrict__ cw,
                                 const float* __restrict__ cb,
                                 __half* __restrict__ u) {
    int idx = blockIdx.x * 256 + threadIdx.x;
    int ncg = DI / 8;                  // 256 channel groups
    int cg = idx & (ncg - 1);
    int strip = idx >> 8;              // 0 .. ROWS/CRS-1
    int d0 = cg * 8;
    int row0 = strip * CRS;
    int b = row0 >> 11;
    int l0 = row0 & (LL - 1);

    float w[8][4], bias[8];
    #pragma unroll
    for (int c = 0; c < 8; c++) {
        float4 wv = reinterpret_cast<const float4*>(cw)[d0 + c];
        w[c][0] = wv.x; w[c][1] = wv.y; w[c][2] = wv.z; w[c][3] = wv.w;
        bias[c] = cb[d0 + c];
    }

    size_t xbase = ((size_t)b * LL + l0) * XZW + d0;
    size_t ubase = ((size_t)b * LL + l0) * DI + d0;

    float xw[3][8];
    #pragma unroll
    for (int k = 0; k < 3; k++) {
        int lk = l0 - 3 + k;
        if (lk >= 0) {
            uint4 v = *reinterpret_cast<const uint4*>(xz + xbase + (size_t)(k - 3) * XZW);
            unpack8(v, xw[k]);
        } else {
            #pragma unroll
            for (int c = 0; c < 8; c++) xw[k][c] = 0.f;
        }
    }

    #pragma unroll
    for (int j = 0; j < CRS; j++) {
        uint4 v = *reinterpret_cast<const uint4*>(xz + xbase + (size_t)j * XZW);
        float cur[8];
        unpack8(v, cur);
        uint4 ov;
        __half2* oh = reinterpret_cast<__half2*>(&ov);
        #pragma unroll
        for (int c = 0; c < 8; c += 2) {
            float a0 = bias[c]   + xw[0][c]  *w[c][0]   + xw[1][c]  *w[c][1]   + xw[2][c]  *w[c][2]   + cur[c]  *w[c][3];
            float a1 = bias[c+1] + xw[0][c+1]*w[c+1][0] + xw[1][c+1]*w[c+1][1] + xw[2][c+1]*w[c+1][2] + cur[c+1]*w[c+1][3];
            float r0 = a0 / (1.f + __expf(-a0));
            float r1 = a1 / (1.f + __expf(-a1));
            oh[c >> 1] = __halves2half2(__float2half_rn(r0), __float2half_rn(r1));
        }
        *reinterpret_cast<uint4*>(u + ubase + (size_t)j * DI) = ov;
        #pragma unroll
        for (int c = 0; c < 8; c++) { xw[0][c] = xw[1][c]; xw[1][c] = xw[2][c]; xw[2][c] = cur[c]; }
    }
}

// ================= chunked parallel scan =================
__device__ __forceinline__ bool load_A(const float* __restrict__ A_log, int d, float* A) {
    bool fast = true;
    #pragma unroll
    for (int n = 0; n < NS; n++) {
        A[n] = -__expf(A_log[d * NS + n]);
        fast = fast && (fabsf(A[n] + (float)(n + 1)) < 1e-5f * (float)(n + 1));
    }
    return fast;
}
__device__ __forceinline__ void pow_tree(float p, float* pw) {
    pw[0] = p;
    #pragma unroll
    for (int k = 1; k < NS; k++) pw[k] = pw[(k - 1) >> 1] * pw[k >> 1];
}

__global__ void scan_pass1(const float* __restrict__ dblr,
                           const __half* __restrict__ delta,
                           const __half* __restrict__ u,
                           const float* __restrict__ A_log,
                           float* __restrict__ S_out,
                           float* __restrict__ hend) {
    int d = blockIdx.x * 256 + threadIdx.x;
    int c = blockIdx.y, b = blockIdx.z;
    float A[NS];
    bool fast = load_A(A_log, d, A);
    float h[NS];
    #pragma unroll
    for (int n = 0; n < NS; n++) h[n] = 0.f;
    float S = 0.f;
    size_t rbase = (size_t)b * LL + (size_t)c * CL;
    for (int j = 0; j < CL; j++) {
        size_t row = rbase + j;
        float dl = __half2float(delta[row * DI + d]);
        float ul = __half2float(u[row * DI + d]);
        const float4* Bp = reinterpret_cast<const float4*>(dblr + row * DBLW + DT);
        float4 B0 = Bp[0], B1 = Bp[1], B2 = Bp[2], B3 = Bp[3];
        float Bv[NS] = {B0.x,B0.y,B0.z,B0.w, B1.x,B1.y,B1.z,B1.w,
                        B2.x,B2.y,B2.z,B2.w, B3.x,B3.y,B3.z,B3.w};
        S += dl;
        float su = dl * ul;
        if (fast) {
            float pw[NS];
            pow_tree(__expf(-dl), pw);
            #pragma unroll
            for (int n = 0; n < NS; n++) h[n] = fmaf(pw[n], h[n], su * Bv[n]);
        } else {
            #pragma unroll
            for (int n = 0; n < NS; n++) h[n] = fmaf(__expf(dl * A[n]), h[n], su * Bv[n]);
        }
    }
    size_t cb = (size_t)b * NC + c;
    S_out[cb * DI + d] = S;
    #pragma unroll
    for (int n = 0; n < NS; n++) hend[(cb * NS + n) * DI + d] = h[n];
}

__global__ void scan_pass2(const float* __restrict__ S_in,
                           const float* __restrict__ hend,
                           const float* __restrict__ A_log,
                           float* __restrict__ hstart) {
    int d = blockIdx.x * 256 + threadIdx.x;
    int b = blockIdx.y;
    float A[NS];
    bool fast = load_A(A_log, d, A);
    float h[NS];
    #pragma unroll
    for (int n = 0; n < NS; n++) h[n] = 0.f;
    for (int c = 0; c < NC; c++) {
        size_t cb = (size_t)b * NC + c;
        #pragma unroll
        for (int n = 0; n < NS; n++) hstart[(cb * NS + n) * DI + d] = h[n];
        float S = S_in[cb * DI + d];
        if (fast) {
            float pw[NS];
            pow_tree(__expf(-S), pw);
            #pragma unroll
            for (int n = 0; n < NS; n++)
                h[n] = fmaf(pw[n], h[n], hend[(cb * NS + n) * DI + d]);
        } else {
            #pragma unroll
            for (int n = 0; n < NS; n++)
                h[n] = fmaf(__expf(S * A[n]), h[n], hend[(cb * NS + n) * DI + d]);
        }
    }
}

__global__ void scan_pass3(const float* __restrict__ dblr,
                           const __half* __restrict__ delta,
                           const __half* __restrict__ u,
                           const __half* __restrict__ xz,
                           const float* __restrict__ A_log,
                           const float* __restrict__ Dskip,
                           const float* __restrict__ hstart,
                           __half* __restrict__ y) {
    int d = blockIdx.x * 256 + threadIdx.x;
    int c = blockIdx.y, b = blockIdx.z;
    float A[NS];
    bool fast = load_A(A_log, d, A);
    float Dd = Dskip[d];
    size_t cb = (size_t)b * NC + c;
    float h[NS];
    #pragma unroll
    for (int n = 0; n < NS; n++) h[n] = hstart[(cb * NS + n) * DI + d];
    size_t rbase = (size_t)b * LL + (size_t)c * CL;
    for (int j = 0; j < CL; j++) {
        size_t row = rbase + j;
        float dl = __half2float(delta[row * DI + d]);
        float ul = __half2float(u[row * DI + d]);
        float zl = __half2float(xz[row * XZW + DI + d]);
        const float4* Bp = reinterpret_cast<const float4*>(dblr + row * DBLW + DT);
        float4 B0 = Bp[0], B1 = Bp[1], B2 = Bp[2], B3 = Bp[3];
        float4 C0 = Bp[4], C1 = Bp[5], C2 = Bp[6], C3 = Bp[7];
        float Bv[NS] = {B0.x,B0.y,B0.z,B0.w, B1.x,B1.y,B1.z,B1.w,
                        B2.x,B2.y,B2.z,B2.w, B3.x,B3.y,B3.z,B3.w};
        float Cv[NS] = {C0.x,C0.y,C0.z,C0.w, C1.x,C1.y,C1.z,C1.w,
                        C2.x,C2.y,C2.z,C2.w, C3.x,C3.y,C3.z,C3.w};
        float su = dl * ul;
        float a0 = 0.f, a1 = 0.f, a2 = 0.f, a3 = 0.f;
        if (fast) {
            float pw[NS];
            pow_tree(__expf(-dl), pw);
            #pragma unroll
            for (int n = 0; n < NS; n++) {
                h[n] = fmaf(pw[n], h[n], su * Bv[n]);
                float* ap = (n & 2) ? ((n & 1) ? &a3 : &a2) : ((n & 1) ? &a1 : &a0);
                *ap = fmaf(h[n], Cv[n], *ap);
            }
        } else {
            #pragma unroll
            for (int n = 0; n < NS; n++) {
                h[n] = fmaf(__expf(dl * A[n]), h[n], su * Bv[n]);
                float* ap = (n & 2) ? ((n & 1) ? &a3 : &a2) : ((n & 1) ? &a1 : &a0);
                *ap = fmaf(h[n], Cv[n], *ap);
            }
        }
        float acc = (a0 + a1) + (a2 + a3);
        float sz = zl / (1.f + __expf(-zl));
        y[row * DI + d] = __float2half_rn(fmaf(ul, Dd, acc) * sz);
    }
}

// ================= launch =================
extern "C" void kernel_launch(void* const* d_in, const int* in_sizes, int n_in,
                              void* d_out, int out_size) {
    const float* x      = (const float*)d_in[0];
    const float* ln_g   = (const float*)d_in[1];
    const float* ln_b   = (const float*)d_in[2];
    const float* W_in   = (const float*)d_in[3];
    const float* conv_w = (const float*)d_in[4];
    const float* conv_b = (const float*)d_in[5];
    const float* W_x    = (const float*)d_in[6];
    const float* W_dt   = (const float*)d_in[7];
    const float* b_dt   = (const float*)d_in[8];
    const float* A_log  = (const float*)d_in[9];
    const float* Dskip  = (const float*)d_in[10];
    const float* W_out  = (const float*)d_in[11];
    float* out = (float*)d_out;

    float *dblp, *dblr, *Ssum, *hend, *hstart;
    __half *xz, *xn, *y, *u, *dt, *delta;
    __half *win, *wout, *wx, *wdt;
    cudaGetSymbolAddress((void**)&xz, g_xz);
    cudaGetSymbolAddress((void**)&dblp, g_dblp);
    cudaGetSymbolAddress((void**)&dblr, g_dblr);
    cudaGetSymbolAddress((void**)&delta, g_delta);
    cudaGetSymbolAddress((void**)&Ssum, g_S);
    cudaGetSymbolAddress((void**)&hend, g_hend);
    cudaGetSymbolAddress((void**)&hstart, g_hstart);
    cudaGetSymbolAddress((void**)&xn, g_xn);
    cudaGetSymbolAddress((void**)&y, g_y);
    cudaGetSymbolAddress((void**)&u, g_u);
    cudaGetSymbolAddress((void**)&dt, g_dt);
    cudaGetSymbolAddress((void**)&win, g_win);
    cudaGetSymbolAddress((void**)&wout, g_wout);
    cudaGetSymbolAddress((void**)&wx, g_wx);
    cudaGetSymbolAddress((void**)&wdt, g_wdt);

    cudaFuncSetAttribute(gemmk<0>, cudaFuncAttributeMaxDynamicSharedMemorySize, SMEM1);
    cudaFuncSetAttribute(gemmk<1>, cudaFuncAttributeMaxDynamicSharedMemorySize, SMEM1);
    cudaFuncSetAttribute(gemmk<2>, cudaFuncAttributeMaxDynamicSharedMemorySize, SMEM1);
    cudaFuncSetAttribute(gemmk<3>, cudaFuncAttributeMaxDynamicSharedMemorySize, SMEM1);

    // 0. fused weight prep (4 transposes) + LayerNorm, one launch
    prep_kernel<<<6528 + ROWS, 256>>>(W_in, W_out, W_x, W_dt, x, ln_g, ln_b,
                                      win, wout, wx, wdt, xn);

    // 1. xz = xn @ W_in   [4096,1024]x[1024,4096] -> fp16   (nkt = 1024/64)
    gemmk<0><<<dim3(XZW/128, ROWS/128, 1), 256, SMEM1>>>(xn, win,
        nullptr, xz, DM, XZW, DM/64, 0);

    // 2. conv + silu -> u fp16 (vectorized, sliding window)
    conv_silu_kernel<<<(ROWS/CRS) * (DI/8) / 256, 256>>>(xz, conv_w, conv_b, u);

    // 3. dbl = u @ W_x   (split-K x4 -> fp32 partials; nkt = 2048/64/4)
    gemmk<3><<<dim3(1, ROWS/128, 4), 256, SMEM1>>>(u, wx,
        nullptr, dblp, DI, DBLW, (DI/64)/4, (size_t)ROWS * DBLW);

    // 4. reduce + dt fp16
    reduce_dbl_kernel<<<(ROWS*DBLW)/256, 256>>>(dblp, dblr, dt);

    // 5. delta = softplus(dt @ W_dt + b_dt) -> fp16   (nkt = 1)
    gemmk<2><<<dim3(DI/128, ROWS/128, 1), 256, SMEM1>>>(dt, wdt,
        b_dt, delta, DT, DI, DT/64, 0);

    // 6. chunked scan -> y fp16
    scan_pass1<<<dim3(DI/256, NC, BB), 256>>>(dblr, delta, u, A_log, Ssum, hend);
    scan_pass2<<<dim3(DI/256, BB), 256>>>(Ssum, hend, A_log, hstart);
    scan_pass3<<<dim3(DI/256, NC, BB), 256>>>(dblr, delta, u, xz, A_log, Dskip,
                                              hstart, y);

    // 7. out = x + y @ W_out   (nkt = 2048/64)
    gemmk<1><<<dim3(DM/128, ROWS/128, 1), 256, SMEM1>>>(y, wout,
        x, out, DI, DM, DI/64, 0);
}

// round 17
// speedup vs baseline: 1.0373x; 1.0003x over previous
#include <cuda_runtime.h>
#include <cuda_fp16.h>
#include <cstdint>
#include <math.h>

// Shapes (fixed): B=2, L=2048, DM=1024, DI=2048, N=16, DC=4, DT=64
#define BB 2
#define LL 2048
#define DM 1024
#define DI 2048
#define NS 16
#define DC 4
#define DT 64
#define ROWS (BB*LL)          // 4096
#define XZW (2*DI)            // 4096
#define DBLW 128              // padded dbl row (dt 0..63 | B 64..79 | C 80..95 | pad)
#define CL 64                 // scan chunk length
#define NC (LL/CL)            // 32 chunks
#define CRS 8                 // conv rows per thread

// ================= scratch (device globals) =================
__device__ __align__(256) __half g_xz[ROWS * XZW];                 // xi | z (fp16)
__device__ __align__(256) float g_dblp[4 * ROWS * DBLW];           // split-K partials
__device__ __align__(256) float g_dblr[ROWS * DBLW];               // reduced
__device__ __align__(256) __half g_delta[ROWS * DI];               // fp16 delta
__device__ __align__(256) float g_S[BB * NC * DI];                 // per-chunk sum(delta)
__device__ __align__(256) float g_hend[BB * NC * NS * DI];
__device__ __align__(256) float g_hstart[BB * NC * NS * DI];
// fp16 operands
__device__ __align__(256) __half g_xn[ROWS * DM];                  // LN out
__device__ __align__(256) __half g_y [ROWS * DI];                  // scan out
__device__ __align__(256) __half g_u [ROWS * DI];                  // conv+silu out
__device__ __align__(256) __half g_dt[ROWS * DT];                  // dt (single)
__device__ __align__(256) __half g_win [XZW * DM];                 // [4096,1024]
__device__ __align__(256) __half g_wout[DM * DI];                  // [1024,2048]
__device__ __align__(256) __half g_wx  [128 * DI];                 // [128,2048] padded
__device__ __align__(256) __half g_wdt [DI * DT];                  // [2048,64]

// ================= PTX helpers (baseline compute_103 ISA only) =================
__device__ __forceinline__ uint32_t smem_u32(const void* p) {
    uint32_t a;
    asm("{ .reg .u64 t; cvta.to.shared.u64 t, %1; cvt.u32.u64 %0, t; }" : "=r"(a) : "l"(p));
    return a;
}
__device__ __forceinline__ void cp_async16(uint32_t sa, const void* ga) {
    asm volatile("cp.async.cg.shared.global [%0], [%1], 16;" :: "r"(sa), "l"(ga));
}
__device__ __forceinline__ void cp_commit() {
    asm volatile("cp.async.commit_group;" ::: "memory");
}
__device__ __forceinline__ void cp_wait1() {
    asm volatile("cp.async.wait_group 1;" ::: "memory");
}
__device__ __forceinline__ void cp_wait0() {
    asm volatile("cp.async.wait_group 0;" ::: "memory");
}
__device__ __forceinline__ void ldsm4(uint32_t* r, uint32_t addr) {
    asm volatile("ldmatrix.sync.aligned.m8n8.x4.shared.b16 {%0,%1,%2,%3}, [%4];"
        : "=r"(r[0]), "=r"(r[1]), "=r"(r[2]), "=r"(r[3]) : "r"(addr));
}
__device__ __forceinline__ void mma_f16(float* d, const uint32_t* a, const uint32_t* b) {
    asm volatile("mma.sync.aligned.m16n8k16.row.col.f32.f16.f16.f32 "
        "{%0,%1,%2,%3}, {%4,%5,%6,%7}, {%8,%9}, {%0,%1,%2,%3};"
        : "+f"(d[0]), "+f"(d[1]), "+f"(d[2]), "+f"(d[3])
        : "r"(a[0]), "r"(a[1]), "r"(a[2]), "r"(a[3]), "r"(b[0]), "r"(b[1]));
}
// SW128 swizzled byte offset for (row, 16B-chunk c in 0..7) in a [rows x 128B] tile
__device__ __forceinline__ uint32_t sw128(int row, int c) {
    return (uint32_t)(row * 128 + ((c ^ (row & 7)) << 4));
}
__device__ __forceinline__ void unpack8(uint4 v, float* f) {
    __half2 h;
    h = *reinterpret_cast<__half2*>(&v.x); f[0] = __low2float(h); f[1] = __high2float(h);
    h = *reinterpret_cast<__half2*>(&v.y); f[2] = __low2float(h); f[3] = __high2float(h);
    h = *reinterpret_cast<__half2*>(&v.z); f[4] = __low2float(h); f[5] = __high2float(h);
    h = *reinterpret_cast<__half2*>(&v.w); f[6] = __low2float(h); f[7] = __high2float(h);
}

// ============ fused weight prep (4 transposes) + LayerNorm ============
__device__ __forceinline__ void trans_body(const float* __restrict__ W,
                                           __half* __restrict__ T,
                                           int K, int N, int bx, int by) {
    __shared__ float t[32][33];
    int tx = threadIdx.x & 31, ty = threadIdx.x >> 5;
    int n = bx * 32 + tx;
    int k0 = by * 32;
    #pragma unroll
    for (int i = 0; i < 4; i++) {
        int k = k0 + ty + i * 8;
        t[ty + i * 8][tx] = (n < N) ? W[(size_t)k * N + n] : 0.f;
    }
    __syncthreads();
    int kw = k0 + tx;
    #pragma unroll
    for (int i = 0; i < 4; i++) {
        int nn = bx * 32 + ty + i * 8;
        T[(size_t)nn * K + kw] = __float2half_rn(t[tx][ty + i * 8]);
    }
}

__device__ __forceinline__ void ln_body(const float* __restrict__ x,
                                        const float* __restrict__ gam,
                                        const float* __restrict__ bet,
                                        __half* __restrict__ xn, int row) {
    const float4* xr = reinterpret_cast<const float4*>(x + (size_t)row * DM);
    int t = threadIdx.x;
    float4 v = xr[t];
    float s  = v.x + v.y + v.z + v.w;
    float ss = v.x*v.x + v.y*v.y + v.z*v.z + v.w*v.w;
    #pragma unroll
    for (int o = 16; o > 0; o >>= 1) {
        s  += __shfl_xor_sync(0xffffffff, s,  o);
        ss += __shfl_xor_sync(0xffffffff, ss, o);
    }
    __shared__ float rs[8], rss[8];
    int wid = t >> 5, lid = t & 31;
    if (lid == 0) { rs[wid] = s; rss[wid] = ss; }
    __syncthreads();
    __shared__ float smu, srstd;
    if (t == 0) {
        float ts = 0.f, tss = 0.f;
        #pragma unroll
        for (int i = 0; i < 8; i++) { ts += rs[i]; tss += rss[i]; }
        float mu = ts / (float)DM;
        float var = tss / (float)DM - mu * mu;
        smu = mu; srstd = rsqrtf(var + 1e-5f);
    }
    __syncthreads();
    float mu = smu, rstd = srstd;
    const float4* g4 = reinterpret_cast<const float4*>(gam);
    const float4* b4 = reinterpret_cast<const float4*>(bet);
    float4 gg = g4[t], bb = b4[t];
    float o0 = (v.x - mu) * rstd * gg.x + bb.x;
    float o1 = (v.y - mu) * rstd * gg.y + bb.y;
    float o2 = (v.z - mu) * rstd * gg.z + bb.z;
    float o3 = (v.w - mu) * rstd * gg.w + bb.w;
    __half2* ph = reinterpret_cast<__half2*>(xn + (size_t)row * DM);
    ph[t*2]   = __halves2half2(__float2half_rn(o0), __float2half_rn(o1));
    ph[t*2+1] = __halves2half2(__float2half_rn(o2), __float2half_rn(o3));
}

__global__ void prep_kernel(const float* __restrict__ W_in,
                            const float* __restrict__ W_out,
                            const float* __restrict__ W_x,
                            const float* __restrict__ W_dt,
                            const float* __restrict__ x,
                            const float* __restrict__ ln_g,
                            const float* __restrict__ ln_b,
                            __half* __restrict__ win,
                            __half* __restrict__ wout,
                            __half* __restrict__ wx,
                            __half* __restrict__ wdt,
                            __half* __restrict__ xn) {
    int bid = blockIdx.x;
    if (bid < 4096) {
        trans_body(W_in, win, DM, XZW, bid & 127, bid >> 7);
    } else if (bid < 6144) {
        int b = bid - 4096;
        trans_body(W_out, wout, DI, DM, b & 31, b >> 5);
    } else if (bid < 6400) {
        int b = bid - 6144;
        trans_body(W_x, wx, DI, 96, b & 3, b >> 2);
    } else if (bid < 6528) {
        int b = bid - 6400;
        trans_body(W_dt, wdt, DT, DI, b & 63, b >> 6);
    } else {
        ln_body(x, ln_g, ln_b, xn, bid - 6528);
    }
}

// ================= unified fp16 GEMM, BK=64, 1 mma pass =================
// EPI 0: fp16 out. 1: fp32 out += E[off]. 2: softplus(v+E[col]) -> fp16. 3: fp32.
#define STG1 32768
#define SMEM1 (3 * STG1)
template<int EPI>
__global__ void __launch_bounds__(256, 2) gemmk(
    const __half* __restrict__ A, const __half* __restrict__ B,
    const float* __restrict__ E, void* __restrict__ Cv,
    int lda, int ldc, int nkt, size_t zstride) {
    extern __shared__ __align__(128) char sm[];
    const int tid = threadIdx.x, lane = tid & 31, wid = tid >> 5;
    const int m0 = blockIdx.y * 128, n0 = blockIdx.x * 128;
    const int wm = (wid >> 2) * 64, wn = (wid & 3) * 32;
    const int kt0 = blockIdx.z * nkt;
    const size_t coff = (size_t)blockIdx.z * zstride;
    const uint32_t sb = smem_u32(sm);

    float d[4][4][4];
    #pragma unroll
    for (int a = 0; a < 4; a++)
        #pragma unroll
        for (int b = 0; b < 4; b++)
            #pragma unroll
            for (int c = 0; c < 4; c++) d[a][b][c] = 0.f;

    // stage: A [128 x 64 half] 16KB, B [128 x 64 half] 16KB; 128B rows SW128.
    auto load_tile = [&](int kt, int stage) {
        uint32_t dst = sb + stage * STG1;
        #pragma unroll
        for (int j = 0; j < 8; j++) {
            int chunk = tid + j * 256;        // 0..2047
            int t = chunk >> 10;              // 0:A 1:B (uniform per j)
            int w = chunk & 1023;
            int row = w >> 3, c = w & 7;
            const __half* src = (t == 0) ? A : B;
            int g0 = (t == 0 ? m0 : n0) + row;
            const void* gp = (const char*)(src + (size_t)g0 * lda + (kt0 + kt) * 64) + c * 16;
            cp_async16(dst + t * 16384 + sw128(row, c), gp);
        }
        cp_commit();
    };

    load_tile(0, 0);
    if (nkt > 1) load_tile(1, 1);

    const int lrow = lane & 15, lk = lane >> 4;
    for (int i = 0; i < nkt; i++) {
        if (i + 1 < nkt) cp_wait1(); else cp_wait0();
        __syncthreads();
        if (i + 2 < nkt) load_tile(i + 2, (i + 2) % 3);

        uint32_t base = sb + (i % 3) * STG1;
        #pragma unroll
        for (int ks = 0; ks < 4; ks++) {
            uint32_t a[4][4], bf[4][2];
            #pragma unroll
            for (int mi = 0; mi < 4; mi++)
                ldsm4(a[mi], base + sw128(wm + mi * 16 + lrow, ks * 2 + lk));
            #pragma unroll
            for (int nj = 0; nj < 2; nj++) {
                uint32_t t4[4];
                ldsm4(t4, base + 16384 + sw128(wn + nj * 16 + lrow, ks * 2 + lk));
                bf[nj*2][0] = t4[0]; bf[nj*2][1] = t4[2];
                bf[nj*2+1][0] = t4[1]; bf[nj*2+1][1] = t4[3];
            }
            #pragma unroll
            for (int mi = 0; mi < 4; mi++)
                #pragma unroll
                for (int ni = 0; ni < 4; ni++)
                    mma_f16(d[mi][ni], a[mi], bf[ni]);
        }
    }

    #pragma unroll
    for (int mi = 0; mi < 4; mi++) {
        #pragma unroll
        for (int ni = 0; ni < 4; ni++) {
            int r = m0 + wm + mi * 16 + (lane >> 2);
            int col = n0 + wn + ni * 8 + (lane & 3) * 2;
            #pragma unroll
            for (int h = 0; h < 2; h++) {
                int rr = r + h * 8;
                float v0 = d[mi][ni][h*2], v1 = d[mi][ni][h*2+1];
                size_t off = coff + (size_t)rr * ldc + col;
                if (EPI == 0) {
                    __half* C = (__half*)Cv;
                    *reinterpret_cast<__half2*>(C + off) =
                        __halves2half2(__float2half_rn(v0), __float2half_rn(v1));
                } else if (EPI == 1) {
                    float* C = (float*)Cv;
                    v0 += E[off]; v1 += E[off + 1];
                    *reinterpret_cast<float2*>(C + off) = make_float2(v0, v1);
                } else if (EPI == 2) {
                    float a0 = v0 + E[col], a1 = v1 + E[col + 1];
                    v0 = (a0 > 20.f) ? a0 : __logf(1.f + __expf(a0));
                    v1 = (a1 > 20.f) ? a1 : __logf(1.f + __expf(a1));
                    __half* C = (__half*)Cv;
                    *reinterpret_cast<__half2*>(C + off) =
                        __halves2half2(__float2half_rn(v0), __float2half_rn(v1));
                } else {
                    float* C = (float*)Cv;
                    *reinterpret_cast<float2*>(C + off) = make_float2(v0, v1);
                }
            }
        }
    }
}

// ============ reduce split-K partials -> dblr; dt -> fp16 ============
__global__ void reduce_dbl_kernel(const float* __restrict__ dblp,
                                  float* __restrict__ dblr,
                                  __half* __restrict__ dt) {
    int i = blockIdx.x * 256 + threadIdx.x;
    if (i >= ROWS * DBLW) return;
    float s = dblp[i] + dblp[i + ROWS*DBLW] + dblp[i + 2*ROWS*DBLW] + dblp[i + 3*ROWS*DBLW];
    dblr[i] = s;
    int col = i & (DBLW - 1);
    if (col < DT) {
        int row = i >> 7;
        dt[row * DT + col] = __float2half_rn(s);
    }
}

// ======== vectorized depthwise conv + SiLU -> u (8 ch x 8 rows / thread) ========
__global__ void conv_silu_kernel(const __half* __restrict__ xz,
                                 const float* __restrict__ cw,
                                 const float* __restrict__ cb,
                                 __half* __restrict__ u) {
    int idx = blockIdx.x * 256 + threadIdx.x;
    int ncg = DI / 8;                  // 256 channel groups
    int cg = idx & (ncg - 1);
    int strip = idx >> 8;              // 0 .. ROWS/CRS-1
    int d0 = cg * 8;
    int row0 = strip * CRS;
    int b = row0 >> 11;
    int l0 = row0 & (LL - 1);

    float w[8][4], bias[8];
    #pragma unroll
    for (int c = 0; c < 8; c++) {
        float4 wv = reinterpret_cast<const float4*>(cw)[d0 + c];
        w[c][0] = wv.x; w[c][1] = wv.y; w[c][2] = wv.z; w[c][3] = wv.w;
        bias[c] = cb[d0 + c];
    }

    size_t xbase = ((size_t)b * LL + l0) * XZW + d0;
    size_t ubase = ((size_t)b * LL + l0) * DI + d0;

    float xw[3][8];
    #pragma unroll
    for (int k = 0; k < 3; k++) {
        int lk = l0 - 3 + k;
        if (lk >= 0) {
            uint4 v = *reinterpret_cast<const uint4*>(xz + xbase + (size_t)(k - 3) * XZW);
            unpack8(v, xw[k]);
        } else {
            #pragma unroll
            for (int c = 0; c < 8; c++) xw[k][c] = 0.f;
        }
    }

    #pragma unroll
    for (int j = 0; j < CRS; j++) {
        uint4 v = *reinterpret_cast<const uint4*>(xz + xbase + (size_t)j * XZW);
        float cur[8];
        unpack8(v, cur);
        uint4 ov;
        __half2* oh = reinterpret_cast<__half2*>(&ov);
        #pragma unroll
        for (int c = 0; c < 8; c += 2) {
            float a0 = bias[c]   + xw[0][c]  *w[c][0]   + xw[1][c]  *w[c][1]   + xw[2][c]  *w[c][2]   + cur[c]  *w[c][3];
            float a1 = bias[c+1] + xw[0][c+1]*w[c+1][0] + xw[1][c+1]*w[c+1][1] + xw[2][c+1]*w[c+1][2] + cur[c+1]*w[c+1][3];
            float r0 = a0 / (1.f + __expf(-a0));
            float r1 = a1 / (1.f + __expf(-a1));
            oh[c >> 1] = __halves2half2(__float2half_rn(r0), __float2half_rn(r1));
        }
        *reinterpret_cast<uint4*>(u + ubase + (size_t)j * DI) = ov;
        #pragma unroll
        for (int c = 0; c < 8; c++) { xw[0][c] = xw[1][c]; xw[1][c] = xw[2][c]; xw[2][c] = cur[c]; }
    }
}

// ================= chunked parallel scan =================
__device__ __forceinline__ bool load_A(const float* __restrict__ A_log, int d, float* A) {
    bool fast = true;
    #pragma unroll
    for (int n = 0; n < NS; n++) {
        A[n] = -__expf(A_log[d * NS + n]);
        fast = fast && (fabsf(A[n] + (float)(n + 1)) < 1e-5f * (float)(n + 1));
    }
    return fast;
}
__device__ __forceinline__ void pow_tree(float p, float* pw) {
    pw[0] = p;
    #pragma unroll
    for (int k = 1; k < NS; k++) pw[k] = pw[(k - 1) >> 1] * pw[k >> 1];
}

__global__ void scan_pass1(const float* __restrict__ dblr,
                           const __half* __restrict__ delta,
                           const __half* __restrict__ u,
                           const float* __restrict__ A_log,
                           float* __restrict__ S_out,
                           float* __restrict__ hend) {
    int d = blockIdx.x * 256 + threadIdx.x;
    int c = blockIdx.y, b = blockIdx.z;
    float A[NS];
    bool fast = load_A(A_log, d, A);
    float h[NS];
    #pragma unroll
    for (int n = 0; n < NS; n++) h[n] = 0.f;
    float S = 0.f;
    size_t rbase = (size_t)b * LL + (size_t)c * CL;
    for (int j = 0; j < CL; j++) {
        size_t row = rbase + j;
        float dl = __half2float(delta[row * DI + d]);
        float ul = __half2float(u[row * DI + d]);
        const float4* Bp = reinterpret_cast<const float4*>(dblr + row * DBLW + DT);
        float4 B0 = Bp[0], B1 = Bp[1], B2 = Bp[2], B3 = Bp[3];
        float Bv[NS] = {B0.x,B0.y,B0.z,B0.w, B1.x,B1.y,B1.z,B1.w,
                        B2.x,B2.y,B2.z,B2.w, B3.x,B3.y,B3.z,B3.w};
        S += dl;
        float su = dl * ul;
        if (fast) {
            float pw[NS];
            pow_tree(__expf(-dl), pw);
            #pragma unroll
            for (int n = 0; n < NS; n++) h[n] = fmaf(pw[n], h[n], su * Bv[n]);
        } else {
            #pragma unroll
            for (int n = 0; n < NS; n++) h[n] = fmaf(__expf(dl * A[n]), h[n], su * Bv[n]);
        }
    }
    size_t cb = (size_t)b * NC + c;
    S_out[cb * DI + d] = S;
    #pragma unroll
    for (int n = 0; n < NS; n++) hend[(cb * NS + n) * DI + d] = h[n];
}

__global__ void scan_pass2(const float* __restrict__ S_in,
                           const float* __restrict__ hend,
                           const float* __restrict__ A_log,
                           float* __restrict__ hstart) {
    int d = blockIdx.x * 256 + threadIdx.x;
    int b = blockIdx.y;
    float A[NS];
    bool fast = load_A(A_log, d, A);
    float h[NS];
    #pragma unroll
    for (int n = 0; n < NS; n++) h[n] = 0.f;
    for (int c = 0; c < NC; c++) {
        size_t cb = (size_t)b * NC + c;
        #pragma unroll
        for (int n = 0; n < NS; n++) hstart[(cb * NS + n) * DI + d] = h[n];
        float S = S_in[cb * DI + d];
        if (fast) {
            float pw[NS];
            pow_tree(__expf(-S), pw);
            #pragma unroll
            for (int n = 0; n < NS; n++)
                h[n] = fmaf(pw[n], h[n], hend[(cb * NS + n) * DI + d]);
        } else {
            #pragma unroll
            for (int n = 0; n < NS; n++)
                h[n] = fmaf(__expf(S * A[n]), h[n], hend[(cb * NS + n) * DI + d]);
        }
    }
}

__global__ void scan_pass3(const float* __restrict__ dblr,
                           const __half* __restrict__ delta,
                           const __half* __restrict__ u,
                           const __half* __restrict__ xz,
                           const float* __restrict__ A_log,
                           const float* __restrict__ Dskip,
                           const float* __restrict__ hstart,
                           __half* __restrict__ y) {
    int d = blockIdx.x * 256 + threadIdx.x;
    int c = blockIdx.y, b = blockIdx.z;
    float A[NS];
    bool fast = load_A(A_log, d, A);
    float Dd = Dskip[d];
    size_t cb = (size_t)b * NC + c;
    float h[NS];
    #pragma unroll
    for (int n = 0; n < NS; n++) h[n] = hstart[(cb * NS + n) * DI + d];
    size_t rbase = (size_t)b * LL + (size_t)c * CL;
    for (int j = 0; j < CL; j++) {
        size_t row = rbase + j;
        float dl = __half2float(delta[row * DI + d]);
        float ul = __half2float(u[row * DI + d]);
        float zl = __half2float(xz[row * XZW + DI + d]);
        const float4* Bp = reinterpret_cast<const float4*>(dblr + row * DBLW + DT);
        float4 B0 = Bp[0], B1 = Bp[1], B2 = Bp[2], B3 = Bp[3];
        float4 C0 = Bp[4], C1 = Bp[5], C2 = Bp[6], C3 = Bp[7];
        float Bv[NS] = {B0.x,B0.y,B0.z,B0.w, B1.x,B1.y,B1.z,B1.w,
                        B2.x,B2.y,B2.z,B2.w, B3.x,B3.y,B3.z,B3.w};
        float Cv[NS] = {C0.x,C0.y,C0.z,C0.w, C1.x,C1.y,C1.z,C1.w,
                        C2.x,C2.y,C2.z,C2.w, C3.x,C3.y,C3.z,C3.w};
        float su = dl * ul;
        float a0 = 0.f, a1 = 0.f, a2 = 0.f, a3 = 0.f;
        if (fast) {
            float pw[NS];
            pow_tree(__expf(-dl), pw);
            #pragma unroll
            for (int n = 0; n < NS; n++) {
                h[n] = fmaf(pw[n], h[n], su * Bv[n]);
                float* ap = (n & 2) ? ((n & 1) ? &a3 : &a2) : ((n & 1) ? &a1 : &a0);
                *ap = fmaf(h[n], Cv[n], *ap);
            }
        } else {
            #pragma unroll
            for (int n = 0; n < NS; n++) {
                h[n] = fmaf(__expf(dl * A[n]), h[n], su * Bv[n]);
                float* ap = (n & 2) ? ((n & 1) ? &a3 : &a2) : ((n & 1) ? &a1 : &a0);
                *ap = fmaf(h[n], Cv[n], *ap);
            }
        }
        float acc = (a0 + a1) + (a2 + a3);
        float sz = zl / (1.f + __expf(-zl));
        y[row * DI + d] = __float2half_rn(fmaf(ul, Dd, acc) * sz);
    }
}

// ================= launch =================
extern "C" void kernel_launch(void* const* d_in, const int* in_sizes, int n_in,
                              void* d_out, int out_size) {
    const float* x      = (const float*)d_in[0];
    const float* ln_g   = (const float*)d_in[1];
    const float* ln_b   = (const float*)d_in[2];
    const float* W_in   = (const float*)d_in[3];
    const float* conv_w = (const float*)d_in[4];
    const float* conv_b = (const float*)d_in[5];
    const float* W_x    = (const float*)d_in[6];
    const float* W_dt   = (const float*)d_in[7];
    const float* b_dt   = (const float*)d_in[8];
    const float* A_log  = (const float*)d_in[9];
    const float* Dskip  = (const float*)d_in[10];
    const float* W_out  = (const float*)d_in[11];
    float* out = (float*)d_out;

    float *dblp, *dblr, *Ssum, *hend, *hstart;
    __half *xz, *xn, *y, *u, *dt, *delta;
    __half *win, *wout, *wx, *wdt;
    cudaGetSymbolAddress((void**)&xz, g_xz);
    cudaGetSymbolAddress((void**)&dblp, g_dblp);
    cudaGetSymbolAddress((void**)&dblr, g_dblr);
    cudaGetSymbolAddress((void**)&delta, g_delta);
    cudaGetSymbolAddress((void**)&Ssum, g_S);
    cudaGetSymbolAddress((void**)&hend, g_hend);
    cudaGetSymbolAddress((void**)&hstart, g_hstart);
    cudaGetSymbolAddress((void**)&xn, g_xn);
    cudaGetSymbolAddress((void**)&y, g_y);
    cudaGetSymbolAddress((void**)&u, g_u);
    cudaGetSymbolAddress((void**)&dt, g_dt);
    cudaGetSymbolAddress((void**)&win, g_win);
    cudaGetSymbolAddress((void**)&wout, g_wout);
    cudaGetSymbolAddress((void**)&wx, g_wx);
    cudaGetSymbolAddress((void**)&wdt, g_wdt);

    cudaFuncSetAttribute(gemmk<0>, cudaFuncAttributeMaxDynamicSharedMemorySize, SMEM1);
    cudaFuncSetAttribute(gemmk<1>, cudaFuncAttributeMaxDynamicSharedMemorySize, SMEM1);
    cudaFuncSetAttribute(gemmk<2>, cudaFuncAttributeMaxDynamicSharedMemorySize, SMEM1);
    cudaFuncSetAttribute(gemmk<3>, cudaFuncAttributeMaxDynamicSharedMemorySize, SMEM1);

    // 0. fused weight prep (4 transposes) + LayerNorm, one launch
    prep_kernel<<<6528 + ROWS, 256>>>(W_in, W_out, W_x, W_dt, x, ln_g, ln_b,
                                      win, wout, wx, wdt, xn);

    // 1. xz = xn @ W_in   [4096,1024]x[1024,4096] -> fp16   (nkt = 1024/64)
    gemmk<0><<<dim3(XZW/128, ROWS/128, 1), 256, SMEM1>>>(xn, win,
        nullptr, xz, DM, XZW, DM/64, 0);

    // 2. conv + silu -> u fp16 (vectorized, sliding window)
    conv_silu_kernel<<<(ROWS/CRS) * (DI/8) / 256, 256>>>(xz, conv_w, conv_b, u);

    // 3. dbl = u @ W_x   (split-K x4 -> fp32 partials; nkt = 2048/64/4)
    gemmk<3><<<dim3(1, ROWS/128, 4), 256, SMEM1>>>(u, wx,
        nullptr, dblp, DI, DBLW, (DI/64)/4, (size_t)ROWS * DBLW);

    // 4. reduce + dt fp16
    reduce_dbl_kernel<<<(ROWS*DBLW)/256, 256>>>(dblp, dblr, dt);

    // 5. delta = softplus(dt @ W_dt + b_dt) -> fp16   (nkt = 1)
    gemmk<2><<<dim3(DI/128, ROWS/128, 1), 256, SMEM1>>>(dt, wdt,
        b_dt, delta, DT, DI, DT/64, 0);

    // 6. chunked scan -> y fp16
    scan_pass1<<<dim3(DI/256, NC, BB), 256>>>(dblr, delta, u, A_log, Ssum, hend);
    scan_pass2<<<dim3(DI/256, BB), 256>>>(Ssum, hend, A_log, hstart);
    scan_pass3<<<dim3(DI/256, NC, BB), 256>>>(dblr, delta, u, xz, A_log, Dskip,
                                              hstart, y);

    // 7. out = x + y @ W_out   (nkt = 2048/64)
    gemmk<1><<<dim3(DM/128, ROWS/128, 1), 256, SMEM1>>>(y, wout,
        x, out, DI, DM, DI/64, 0);
}